// round 16
// baseline (speedup 1.0000x reference)
#include <cuda_runtime.h>
#include <math.h>
#include <stdint.h>

// Problem constants
#define Bz  64
#define Tz  512
#define Iz  256
#define Hz  512
#define FH  2048   // 4*H
#define NCTA 148
#define HB  (Hz * Bz)
#define OUTBASE (Bz * Tz * Hz)   // 16777216

// ---------------- device scratch ----------------
__device__ float g_A0[(size_t)Tz * FH * Bz];   // x@Wx0+bh0, [t][col][b]
__device__ float g_h0[2 * HB];                 // parity-buffered states, [H][B]
__device__ float g_h1[2 * HB];
__device__ float g_s0[2 * HB];
__device__ unsigned g_bar;

__device__ __forceinline__ float sigf(float x) { return 1.0f / (1.0f + __expf(-x)); }

// 3-way tf32 split: x = h + m + l (each tf32), residual ~2^-34
__device__ __forceinline__ void split3(float x, uint32_t& h, uint32_t& m, uint32_t& l) {
    asm("cvt.rna.tf32.f32 %0, %1;" : "=r"(h) : "f"(x));
    float r = x - __uint_as_float(h);
    asm("cvt.rna.tf32.f32 %0, %1;" : "=r"(m) : "f"(r));
    float r2 = r - __uint_as_float(m);
    asm("cvt.rna.tf32.f32 %0, %1;" : "=r"(l) : "f"(r2));
}

#define MMA8(d, A, b0, b1) \
    asm volatile("mma.sync.aligned.m16n8k8.row.col.f32.tf32.tf32.f32 " \
        "{%0,%1,%2,%3},{%4,%5,%6,%7},{%8,%9},{%0,%1,%2,%3};" \
        : "+f"((d)[0]), "+f"((d)[1]), "+f"((d)[2]), "+f"((d)[3]) \
        : "r"((A)[0]), "r"((A)[1]), "r"((A)[2]), "r"((A)[3]), "r"(b0), "r"(b1))

__device__ __forceinline__ void grid_bar(unsigned target) {
    __syncthreads();
    if (threadIdx.x == 0) {
        asm volatile("red.release.gpu.global.add.u32 [%0], 1;" :: "l"(&g_bar) : "memory");
        unsigned v;
        do { asm volatile("ld.acquire.gpu.global.u32 %0, [%1];" : "=r"(v) : "l"(&g_bar) : "memory"); }
        while (v < target);
    }
    __syncthreads();
}

// ---------------- phase A (+ state init in y==0 blocks) ----------------
__global__ __launch_bounds__(128) void k_phaseA(const float* __restrict__ x,
                                                const float* __restrict__ Wx0,
                                                const float* __restrict__ bh0) {
    __shared__ float ws[64][64];
    __shared__ float xs[64][68];
    int colTile = blockIdx.x, t = blockIdx.y, tid = threadIdx.x;

    if (t == 0) {
        int g = colTile * 128 + tid;
        if (g == 0) g_bar = 0;
        for (int i = g; i < 2 * HB; i += 4096) { g_h0[i] = 0.f; g_h1[i] = 0.f; g_s0[i] = 0.f; }
    }

    int tc = tid & 7, tb = tid >> 3;
    int colBase = colTile * 64;
    float acc[8][4];
#pragma unroll
    for (int a = 0; a < 8; a++)
#pragma unroll
        for (int b = 0; b < 4; b++) acc[a][b] = 0.f;

    for (int kt = 0; kt < 4; kt++) {
        int kb = kt * 64;
        for (int i = tid; i < 64 * 16; i += 128) {
            int row = i >> 4, c4 = (i & 15) << 2;
            *(float4*)&ws[row][c4] = *(const float4*)&Wx0[(size_t)(kb + row) * FH + colBase + c4];
        }
        {
            int b = tid >> 1, half = tid & 1;
            const float* xr = x + ((size_t)b * Tz + t) * Iz + kb + half * 32;
#pragma unroll
            for (int q = 0; q < 8; q++) {
                float4 v = *(const float4*)(xr + q * 4);
                int i0 = half * 32 + q * 4;
                xs[i0][b] = v.x; xs[i0 + 1][b] = v.y; xs[i0 + 2][b] = v.z; xs[i0 + 3][b] = v.w;
            }
        }
        __syncthreads();
#pragma unroll 16
        for (int k = 0; k < 64; k++) {
            float4 w0 = *(const float4*)&ws[k][tc * 8];
            float4 w1 = *(const float4*)&ws[k][tc * 8 + 4];
            float4 hv = *(const float4*)&xs[k][tb * 4];
            float wr[8] = {w0.x, w0.y, w0.z, w0.w, w1.x, w1.y, w1.z, w1.w};
            float hr[4] = {hv.x, hv.y, hv.z, hv.w};
#pragma unroll
            for (int ci = 0; ci < 8; ci++)
#pragma unroll
                for (int bi = 0; bi < 4; bi++) acc[ci][bi] += wr[ci] * hr[bi];
        }
        __syncthreads();
    }
    float* outp = g_A0 + (size_t)t * (FH * Bz) + (size_t)colBase * Bz;
#pragma unroll
    for (int ci = 0; ci < 8; ci++) {
        float bias = bh0[colBase + tc * 8 + ci];
        float4 v = {acc[ci][0] + bias, acc[ci][1] + bias, acc[ci][2] + bias, acc[ci][3] + bias};
        *(float4*)&outp[(tc * 8 + ci) * Bz + tb * 4] = v;
    }
}

// ---------------- persistent fused kernel: 148 CTAs x 256 threads ----------------
// smem floats: wt[2][16384] fragment-major weights | hbuf[2][2560] (stride 40) | gs[8*1056]
#define SMEM_FLOATS (2 * 16384 + 2 * 2560 + 8 * 1056)
#define SMEM_BYTES  (SMEM_FLOATS * 4)

__global__ __launch_bounds__(256) void k_persist(
    const float* __restrict__ Wh0, const float* __restrict__ Wx1,
    const float* __restrict__ Wh1, const float* __restrict__ bh1,
    float* __restrict__ out)
{
    extern __shared__ float smem[];
    float* wt   = smem;
    float* hbuf = smem + 2 * 16384;
    float* gs   = smem + 2 * 16384 + 2 * 2560;

    const int tid  = threadIdx.x;
    const int cta  = blockIdx.x;
    const int lane = tid & 31;
    const int warp = tid >> 5;
    const int tq   = lane & 3;     // threadID in group (k)
    const int gq   = lane >> 2;    // groupID (m or n)

    // ---- fixed job list (same as R12) ----
    int nb, bj0;
    if (cta < 88) { nb = 3; bj0 = 3 * cta; } else { nb = 2; bj0 = 264 + 2 * (cta - 88); }
    int jhalf[3], jtype[3], jj0[3], jslot[3];
    int nslots = 0, slot_w[2];
    for (int u = 0; u < nb; u++) {
        int bj = bj0 + u, w = bj >> 1;
        jhalf[u] = bj & 1;
        jtype[u] = (w >= 64);
        jj0[u]   = jtype[u] ? (w - 64) * 4 : w * 8;
        int s = -1;
        for (int q = 0; q < nslots; q++) if (slot_w[q] == w) s = q;
        if (s < 0) { s = nslots; slot_w[nslots++] = w; }
        jslot[u] = s;
    }
    // ---- prepack weight tiles into fragment-major smem (once) ----
    for (int s = 0; s < nslots; s++) {
        int w = slot_w[s];
        float* wd = wt + s * 16384;
        if (w < 64) {          // L0: 32 cols (c=cg*8+jj), K=512, 2 M-tiles
            int j0 = w * 8;
            for (int idx = tid; idx < 16384; idx += 256) {
                int q = idx & 3, ln = (idx >> 2) & 31, mt = (idx >> 7) & 1, kst = idx >> 8;
                int g = ln >> 2, t4 = ln & 3;
                int c = mt * 16 + g + (q & 1) * 8;
                int k = kst * 8 + t4 + (q >> 1) * 4;
                int cg = c >> 3, jj = c & 7;
                wd[idx] = Wh0[(size_t)k * FH + cg * 512 + j0 + jj];
            }
        } else {               // L1: 16 cols (c=cg*4+jj), K=1024, 1 M-tile
            int j0 = (w - 64) * 4;
            for (int idx = tid; idx < 16384; idx += 256) {
                int q = idx & 3, ln = (idx >> 2) & 31, kst = idx >> 7;
                int g = ln >> 2, t4 = ln & 3;
                int c = g + (q & 1) * 8;
                int k = kst * 8 + t4 + (q >> 1) * 4;
                int cg = c >> 2, jj = c & 3;
                int col = cg * 512 + j0 + jj;
                wd[idx] = (k < 512) ? Wx1[(size_t)k * FH + col] : Wh1[(size_t)(k - 512) * FH + col];
            }
        }
    }
    __syncthreads();

    float carr[3];
#pragma unroll
    for (int u = 0; u < 3; u++) carr[u] = 0.f;
    unsigned ph = 0;

    for (int t = 0; t <= Tz; t++) {
        for (int u = 0; u < nb; u++) {
            int type = jtype[u];
            bool valid = type ? (t > 0) : (t < Tz);
            if (!valid) continue;                      // CTA-uniform
            int half = jhalf[u], j0 = jj0[u];
            const float* wd = wt + jslot[u] * 16384;
            int nch = type ? 16 : 8;
            int tau = t - type;

            // ---- gate-tail operand prefetch (same as R12) ----
            float a0r[4], sold = 0.f, biasr[4];
            if (!type) {
                int jj = tid >> 5, lb = tid & 31;
                int b = half * 32 + lb, j = j0 + jj;
#pragma unroll
                for (int cg = 0; cg < 4; cg++)
                    a0r[cg] = __ldcs(&g_A0[(size_t)t * (FH * Bz) + (cg * 512 + j) * Bz + b]);
                sold = __ldcg(&g_s0[((t + 1) & 1) * HB + j * Bz + b]);
            } else if (tid < 128) {
                int jj = tid >> 5, lb = tid & 31;
                int b = half * 32 + lb, j = j0 + jj;
#pragma unroll
                for (int cg = 0; cg < 4; cg++) biasr[cg] = __ldg(&bh1[cg * 512 + j]);
                sold = __ldcg(&g_s0[((t - 1) & 1) * HB + j * Bz + b]);
            }

            float acc[8][4];
#pragma unroll
            for (int a = 0; a < 8; a++)
#pragma unroll
                for (int b2 = 0; b2 < 4; b2++) acc[a][b2] = 0.f;

            auto chsrc = [&](int ch) -> const float* {
                if (!type) return g_h0 + ((t + 1) & 1) * HB + ch * 64 * Bz + half * 32;
                if (ch < 8) return g_s0 + ((t - 1) & 1) * HB + ch * 64 * Bz + half * 32;
                return g_h1 + (t & 1) * HB + (ch - 8) * 64 * Bz + half * 32;
            };

            float4 r[2];
            {   // load + store chunk 0 (512 float4 over 256 threads), hbuf stride 40
                const float* src = chsrc(0);
#pragma unroll
                for (int m = 0; m < 2; m++) {
                    int idx = tid + m * 256, kl = idx >> 3, s = idx & 7;
                    r[m] = __ldcg((const float4*)&src[kl * Bz + s * 4]);
                }
#pragma unroll
                for (int m = 0; m < 2; m++) {
                    int idx = tid + m * 256, kl = idx >> 3, s = idx & 7;
                    *(float4*)&hbuf[kl * 40 + s * 4] = r[m];
                }
                __syncthreads();
            }

            for (int ch = 0; ch < nch; ch++) {
                if (ch + 1 < nch) {
                    const float* src = chsrc(ch + 1);
#pragma unroll
                    for (int m = 0; m < 2; m++) {
                        int idx = tid + m * 256, kl = idx >> 3, s = idx & 7;
                        r[m] = __ldcg((const float4*)&src[kl * Bz + s * 4]);
                    }
                }
                const float* hb = hbuf + (ch & 1) * 2560;
                int kst = ch * 8 + warp;
                if (!type) {
                    uint32_t ah[2][4], am[2][4], al[2][4];
#pragma unroll
                    for (int mt = 0; mt < 2; mt++) {
                        float4 wa = *(const float4*)&wd[(((kst * 2 + mt) << 5) + lane) << 2];
                        split3(wa.x, ah[mt][0], am[mt][0], al[mt][0]);
                        split3(wa.y, ah[mt][1], am[mt][1], al[mt][1]);
                        split3(wa.z, ah[mt][2], am[mt][2], al[mt][2]);
                        split3(wa.w, ah[mt][3], am[mt][3], al[mt][3]);
                    }
#pragma unroll
                    for (int nt = 0; nt < 4; nt++) {
                        float b0f = hb[(warp * 8 + tq) * 40 + nt * 8 + gq];
                        float b1f = hb[(warp * 8 + tq + 4) * 40 + nt * 8 + gq];
                        uint32_t bh[2], bm[2], bl[2];
                        split3(b0f, bh[0], bm[0], bl[0]);
                        split3(b1f, bh[1], bm[1], bl[1]);
#pragma unroll
                        for (int mt = 0; mt < 2; mt++) {
                            float* d = acc[mt * 4 + nt];
                            MMA8(d, ah[mt], bh[0], bh[1]);
                            MMA8(d, ah[mt], bm[0], bm[1]);
                            MMA8(d, am[mt], bh[0], bh[1]);
                            MMA8(d, am[mt], bm[0], bm[1]);
                            MMA8(d, ah[mt], bl[0], bl[1]);
                            MMA8(d, al[mt], bh[0], bh[1]);
                        }
                    }
                } else {
                    uint32_t ah[4], am[4], al[4];
                    float4 wa = *(const float4*)&wd[((kst << 5) + lane) << 2];
                    split3(wa.x, ah[0], am[0], al[0]);
                    split3(wa.y, ah[1], am[1], al[1]);
                    split3(wa.z, ah[2], am[2], al[2]);
                    split3(wa.w, ah[3], am[3], al[3]);
#pragma unroll
                    for (int nt = 0; nt < 4; nt++) {
                        float b0f = hb[(warp * 8 + tq) * 40 + nt * 8 + gq];
                        float b1f = hb[(warp * 8 + tq + 4) * 40 + nt * 8 + gq];
                        float* d = acc[nt];
                        if (ch < 8) {   // spikes: exact tf32 bit patterns
                            uint32_t b0 = __float_as_uint(b0f), b1 = __float_as_uint(b1f);
                            MMA8(d, ah, b0, b1);
                            MMA8(d, am, b0, b1);
                            MMA8(d, al, b0, b1);
                        } else {
                            uint32_t bh[2], bm[2], bl[2];
                            split3(b0f, bh[0], bm[0], bl[0]);
                            split3(b1f, bh[1], bm[1], bl[1]);
                            MMA8(d, ah, bh[0], bh[1]);
                            MMA8(d, ah, bm[0], bm[1]);
                            MMA8(d, am, bh[0], bh[1]);
                            MMA8(d, am, bm[0], bm[1]);
                            MMA8(d, ah, bl[0], bl[1]);
                            MMA8(d, al, bh[0], bh[1]);
                        }
                    }
                }
                if (ch + 1 < nch) {
                    float* hn = hbuf + ((ch + 1) & 1) * 2560;
#pragma unroll
                    for (int m = 0; m < 2; m++) {
                        int idx = tid + m * 256, kl = idx >> 3, s = idx & 7;
                        *(float4*)&hn[kl * 40 + s * 4] = r[m];
                    }
                }
                __syncthreads();
            }

            // ---- D fragments -> gs (per-warp k-slice partials, [c][b]) ----
            float* gw = gs + warp * 1056;
            if (!type) {
#pragma unroll
                for (int mt = 0; mt < 2; mt++)
#pragma unroll
                    for (int nt = 0; nt < 4; nt++) {
                        float* d = acc[mt * 4 + nt];
                        int c0 = mt * 16 + gq, bb = nt * 8 + 2 * tq;
                        gw[c0 * 33 + bb]       = d[0];
                        gw[c0 * 33 + bb + 1]   = d[1];
                        gw[(c0 + 8) * 33 + bb]     = d[2];
                        gw[(c0 + 8) * 33 + bb + 1] = d[3];
                    }
            } else {
#pragma unroll
                for (int nt = 0; nt < 4; nt++) {
                    float* d = acc[nt];
                    int bb = nt * 8 + 2 * tq;
                    gw[gq * 33 + bb]       = d[0];
                    gw[gq * 33 + bb + 1]   = d[1];
                    gw[(gq + 8) * 33 + bb]     = d[2];
                    gw[(gq + 8) * 33 + bb + 1] = d[3];
                }
            }
            __syncthreads();

            // ---- fused gate tails (identical to R12) ----
            if (!type) {
                int jj = tid >> 5, lb = tid & 31;
                int j = j0 + jj, b = half * 32 + lb;
                float gv[4];
#pragma unroll
                for (int cg = 0; cg < 4; cg++) {
                    float v = a0r[cg];
#pragma unroll
                    for (int w2 = 0; w2 < 8; w2++)
                        v += gs[w2 * 1056 + (cg * 8 + jj) * 33 + lb];
                    gv[cg] = v;
                }
                float cn  = sigf(gv[1]) * carr[u] + sigf(gv[0]) * tanhf(gv[2]);
                float hn  = sigf(gv[3]) * tanhf(cn);
                float mem = sold * 0.2f * (1.0f - sold) + hn;
                float sn  = (mem > 0.5f) ? 1.0f : 0.0f;
                carr[u] = cn;
                __stcg(&g_h0[(t & 1) * HB + j * Bz + b], mem);
                __stcg(&g_s0[(t & 1) * HB + j * Bz + b], sn);
                if (t == Tz - 1) {
                    int bj = b * Hz + j;
                    out[OUTBASE + bj]          = sn;
                    out[OUTBASE + 32768 + bj]  = 0.0f;
                    out[OUTBASE + 65536 + bj]  = mem;
                    out[OUTBASE + 131072 + bj] = cn;
                }
            } else if (tid < 128) {
                int jj = tid >> 5, lb = tid & 31;
                int j = j0 + jj, b = half * 32 + lb;
                float gv[4];
#pragma unroll
                for (int cg = 0; cg < 4; cg++) {
                    float v = biasr[cg];
#pragma unroll
                    for (int w2 = 0; w2 < 8; w2++)
                        v += gs[w2 * 1056 + (cg * 4 + jj) * 33 + lb];
                    gv[cg] = v;
                }
                float cn   = sigf(gv[1]) * carr[u] + sigf(gv[0]) * tanhf(gv[2]);
                float hraw = sigf(gv[3]) * tanhf(cn);
                float h1   = hraw * 0.2f + sold;
                carr[u] = cn;
                __stcg(&g_h1[(tau & 1) * HB + j * Bz + b], h1);
                out[(size_t)b * (Tz * Hz) + tau * Hz + j] = h1;
                if (tau == Tz - 1) {
                    int bj = b * Hz + j;
                    out[OUTBASE + 98304 + bj]  = h1;
                    out[OUTBASE + 163840 + bj] = cn;
                }
            }
            __syncthreads();
        }
        grid_bar(++ph * NCTA);
    }
}

// ---------------- launch: 2 graph nodes ----------------
extern "C" void kernel_launch(void* const* d_in, const int* in_sizes, int n_in,
                              void* d_out, int out_size) {
    const float* x   = (const float*)d_in[0];
    const float* Wx0 = (const float*)d_in[1];
    const float* Wh0 = (const float*)d_in[2];
    const float* bh0 = (const float*)d_in[3];
    const float* Wx1 = (const float*)d_in[4];
    const float* Wh1 = (const float*)d_in[5];
    const float* bh1 = (const float*)d_in[6];
    float* out = (float*)d_out;

    static int smem_set = 0;
    if (!smem_set) {
        cudaFuncSetAttribute(k_persist, cudaFuncAttributeMaxDynamicSharedMemorySize, SMEM_BYTES);
        smem_set = 1;
    }

    k_phaseA<<<dim3(32, Tz), 128>>>(x, Wx0, bh0);
    k_persist<<<NCTA, 256, SMEM_BYTES>>>(Wh0, Wx1, Wh1, bh1, out);
}